// round 1
// baseline (speedup 1.0000x reference)
#include <cuda_runtime.h>

#define BATCH 32
#define CH    128
#define HDIM  128
#define WDIM  128
#define HW    16384        // HDIM*WDIM
#define NB    4
#define KK    9            // 3x3
#define NROWS (NB*CH*KK)   // 4608 rows of w_base

// ---- scratch (device globals; no allocation allowed) ----
__device__ float g_pooled[BATCH * CH];          // channel sums (atomic)
__device__ float g_attn[BATCH * NB];            // softmax sums (atomic)
__device__ float g_bases[(size_t)BATCH * NROWS];// per-sample base kernels

// ============================================================
// init: zero the atomic accumulators
// ============================================================
__global__ void k_init() {
    int idx = blockIdx.x * 256 + threadIdx.x;
    if (idx < BATCH * CH) g_pooled[idx] = 0.f;
    if (idx < BATCH * NB) g_attn[idx]   = 0.f;
}

// ============================================================
// pass 1: fused pooled-sum + attention logits + softmax + spatial mean
// grid (16 chunks, 32 batch), 256 threads; each thread owns 4 pixels.
// ============================================================
__global__ void __launch_bounds__(256) k_stats(
    const float* __restrict__ x,
    const float* __restrict__ w_attn,
    const float* __restrict__ b_attn)
{
    const int b     = blockIdx.y;
    const int chunk = blockIdx.x;     // 0..15, 1024 pixels each
    const int tid   = threadIdx.x;    // 0..255
    const int lane  = tid & 31;

    __shared__ float s_wa[NB * CH];
    for (int i = tid; i < NB * CH; i += 256) s_wa[i] = w_attn[i];
    __syncthreads();

    // float4 base: pixel group (chunk*256 + tid) within each channel plane
    const float4* xb = (const float4*)x
                     + (size_t)b * CH * (HW / 4)
                     + chunk * 256 + tid;

    float acc[NB][4];
    #pragma unroll
    for (int n = 0; n < NB; n++)
        #pragma unroll
        for (int j = 0; j < 4; j++) acc[n][j] = 0.f;

    for (int c = 0; c < CH; c++) {
        float4 v = xb[(size_t)c * (HW / 4)];
        float w0 = s_wa[0 * CH + c];
        float w1 = s_wa[1 * CH + c];
        float w2 = s_wa[2 * CH + c];
        float w3 = s_wa[3 * CH + c];
        acc[0][0] += w0 * v.x; acc[0][1] += w0 * v.y; acc[0][2] += w0 * v.z; acc[0][3] += w0 * v.w;
        acc[1][0] += w1 * v.x; acc[1][1] += w1 * v.y; acc[1][2] += w1 * v.z; acc[1][3] += w1 * v.w;
        acc[2][0] += w2 * v.x; acc[2][1] += w2 * v.y; acc[2][2] += w2 * v.z; acc[2][3] += w2 * v.w;
        acc[3][0] += w3 * v.x; acc[3][1] += w3 * v.y; acc[3][2] += w3 * v.z; acc[3][3] += w3 * v.w;

        // pooled channel sum: warp reduce + one atomic per warp
        float s = v.x + v.y + v.z + v.w;
        #pragma unroll
        for (int o = 16; o > 0; o >>= 1) s += __shfl_down_sync(0xffffffffu, s, o);
        if (lane == 0) atomicAdd(&g_pooled[b * CH + c], s);
    }

    const float bb0 = b_attn[0], bb1 = b_attn[1], bb2 = b_attn[2], bb3 = b_attn[3];
    float ap[NB] = {0.f, 0.f, 0.f, 0.f};
    #pragma unroll
    for (int j = 0; j < 4; j++) {
        float l0 = acc[0][j] + bb0;
        float l1 = acc[1][j] + bb1;
        float l2 = acc[2][j] + bb2;
        float l3 = acc[3][j] + bb3;
        float m  = fmaxf(fmaxf(l0, l1), fmaxf(l2, l3));
        float e0 = __expf(l0 - m);
        float e1 = __expf(l1 - m);
        float e2 = __expf(l2 - m);
        float e3 = __expf(l3 - m);
        float inv = 1.f / (e0 + e1 + e2 + e3);
        ap[0] += e0 * inv; ap[1] += e1 * inv; ap[2] += e2 * inv; ap[3] += e3 * inv;
    }
    #pragma unroll
    for (int n = 0; n < NB; n++) {
        float s = ap[n];
        #pragma unroll
        for (int o = 16; o > 0; o >>= 1) s += __shfl_down_sync(0xffffffffu, s, o);
        if (lane == 0) atomicAdd(&g_attn[b * NB + n], s);
    }
}

// ============================================================
// pass 2: bases[b, row] = dot(w_base[row,:], pooled[b,:]) + b_base[row]
// grid 36 blocks x 128 threads; each thread = one w_base row, ALL 32 batches.
// w_base is read exactly once from HBM.
// ============================================================
__global__ void __launch_bounds__(128) k_bases(
    const float* __restrict__ w_base,
    const float* __restrict__ b_base)
{
    const int row = blockIdx.x * 128 + threadIdx.x;   // 0..4607

    __shared__ float s_pool[BATCH * CH];              // 16 KB, pooled MEANS
    for (int i = threadIdx.x; i < BATCH * CH; i += 128)
        s_pool[i] = g_pooled[i] * (1.0f / HW);
    __syncthreads();

    float acc[BATCH];
    const float bb = b_base[row];
    #pragma unroll
    for (int b = 0; b < BATCH; b++) acc[b] = bb;

    const float4* wr = (const float4*)(w_base + (size_t)row * CH);
    const float4* pp = (const float4*)s_pool;
    for (int c4 = 0; c4 < CH / 4; c4++) {
        float4 wv = wr[c4];
        #pragma unroll
        for (int b = 0; b < BATCH; b++) {
            float4 pv = pp[b * (CH / 4) + c4];   // broadcast LDS
            acc[b] += wv.x * pv.x + wv.y * pv.y + wv.z * pv.z + wv.w * pv.w;
        }
    }
    #pragma unroll
    for (int b = 0; b < BATCH; b++)
        g_bases[(size_t)b * NROWS + row] = acc[b];
}

// ============================================================
// pass 3: per-sample 3x3 conv, reducing over C -> out[b,1,h,w]
// grid (8 tiles_y, 32 batch), 128 threads.
// Tile = 16 rows x 128 cols; thread = 4x4 outputs; warp spans full width.
// Column halos via shuffle (full-width tile => halos are the zero padding).
// ============================================================
#define TILE_ROWS 16
__global__ void __launch_bounds__(128) k_conv(
    const float* __restrict__ x,
    float* __restrict__ out)
{
    const int b    = blockIdx.y;
    const int r0   = blockIdx.x * TILE_ROWS;
    const int tid  = threadIdx.x;
    const int th   = tid >> 5;      // warp id 0..3 -> 4-row band
    const int lane = tid & 31;      // 4 cols each -> 128 wide

    __shared__ float skern[CH * KK];                 // 4.6 KB
    __shared__ float stile[TILE_ROWS + 2][WDIM];     // 9.2 KB

    // build per-sample kernel: kern = sum_n a_n * bases_n  (fold of pass 2b)
    float a[NB];
    #pragma unroll
    for (int n = 0; n < NB; n++)
        a[n] = g_attn[b * NB + n] * (1.0f / HW);
    for (int i = tid; i < CH * KK; i += 128) {
        float s = 0.f;
        #pragma unroll
        for (int n = 0; n < NB; n++)
            s += a[n] * g_bases[(size_t)b * NROWS + n * (CH * KK) + i];
        skern[i] = s;
    }

    float acc[4][4];
    #pragma unroll
    for (int k = 0; k < 4; k++)
        #pragma unroll
        for (int m = 0; m < 4; m++) acc[k][m] = 0.f;

    const float* xb = x + (size_t)b * CH * HW;
    __syncthreads();

    for (int c = 0; c < CH; c++) {
        // stage (TILE_ROWS+2) x 128 input rows for this channel
        const float* xc = xb + (size_t)c * HW;
        for (int j = tid; j < (TILE_ROWS + 2) * 32; j += 128) {
            int i  = j >> 5;            // smem row 0..17
            int f  = j & 31;            // float4 within row
            int gr = r0 - 1 + i;        // global row
            float4 v;
            if (gr >= 0 && gr < HDIM) v = ((const float4*)(xc + (size_t)gr * WDIM))[f];
            else                      v = make_float4(0.f, 0.f, 0.f, 0.f);
            ((float4*)stile[i])[f] = v;
        }
        __syncthreads();

        float kc[KK];
        #pragma unroll
        for (int q = 0; q < KK; q++) kc[q] = skern[c * KK + q];

        #pragma unroll
        for (int ir = 0; ir < 6; ir++) {
            const int srow = th * 4 + ir;
            float4 v = ((const float4*)stile[srow])[lane];
            float u0 = __shfl_up_sync(0xffffffffu, v.w, 1);
            if (lane == 0)  u0 = 0.f;        // col -1 = zero pad
            float u5 = __shfl_down_sync(0xffffffffu, v.x, 1);
            if (lane == 31) u5 = 0.f;        // col 128 = zero pad
            float u[6] = {u0, v.x, v.y, v.z, v.w, u5};
            #pragma unroll
            for (int k = 0; k < 4; k++) {
                const int dy = ir - k;
                if (dy >= 0 && dy <= 2) {
                    #pragma unroll
                    for (int m = 0; m < 4; m++)
                        #pragma unroll
                        for (int dx = 0; dx < 3; dx++)
                            acc[k][m] += u[m + dx] * kc[dy * 3 + dx];
                }
            }
        }
        __syncthreads();
    }

    #pragma unroll
    for (int k = 0; k < 4; k++) {
        int r = r0 + th * 4 + k;
        float4 o = make_float4(acc[k][0], acc[k][1], acc[k][2], acc[k][3]);
        ((float4*)(out + (size_t)b * HW + (size_t)r * WDIM))[lane] = o;
    }
}

// ============================================================
extern "C" void kernel_launch(void* const* d_in, const int* in_sizes, int n_in,
                              void* d_out, int out_size)
{
    const float* x      = (const float*)d_in[0];
    const float* w_base = (const float*)d_in[1];
    const float* b_base = (const float*)d_in[2];
    const float* w_attn = (const float*)d_in[3];
    const float* b_attn = (const float*)d_in[4];
    float* out = (float*)d_out;

    k_init <<<16, 256>>>();
    k_stats<<<dim3(16, BATCH), 256>>>(x, w_attn, b_attn);
    k_bases<<<NROWS / 128, 128>>>(w_base, b_base);
    k_conv <<<dim3(HDIM / TILE_ROWS, BATCH), 128>>>(x, out);
}

// round 4
// speedup vs baseline: 2.7466x; 2.7466x over previous
#include <cuda_runtime.h>
#include <cstdint>

#define BATCH 32
#define CH    128
#define HDIM  128
#define WDIM  128
#define HW    16384        // HDIM*WDIM
#define NB    4
#define KK    9            // 3x3
#define NROWS (NB*CH*KK)   // 4608 rows of w_base
#define NGRP  4            // channel groups in conv
#define CG    (CH/NGRP)    // 32 channels per group

// ---- scratch (device globals; no allocation allowed) ----
__device__ float g_pooled[BATCH * CH];              // channel sums (atomic)
__device__ float g_attn[BATCH * NB];                // softmax sums (atomic)
__device__ float g_bases[(size_t)BATCH * NROWS];    // per-sample base kernels
__device__ float g_part[(size_t)NGRP * BATCH * HW]; // conv partials (8 MB)

// ============================================================
// init: zero the atomic accumulators
// ============================================================
__global__ void k_init() {
    int idx = blockIdx.x * 256 + threadIdx.x;
    if (idx < BATCH * CH) g_pooled[idx] = 0.f;
    if (idx < BATCH * NB) g_attn[idx]   = 0.f;
}

// ============================================================
// pass 1: fused pooled-sum + attention logits + softmax + spatial mean
// grid (16 chunks, 32 batch), 256 threads; each thread owns 4 pixels.
// ============================================================
__global__ void __launch_bounds__(256) k_stats(
    const float* __restrict__ x,
    const float* __restrict__ w_attn,
    const float* __restrict__ b_attn)
{
    const int b     = blockIdx.y;
    const int chunk = blockIdx.x;     // 0..15, 1024 pixels each
    const int tid   = threadIdx.x;    // 0..255
    const int lane  = tid & 31;

    __shared__ float s_wa[NB * CH];
    for (int i = tid; i < NB * CH; i += 256) s_wa[i] = w_attn[i];
    __syncthreads();

    const float4* xb = (const float4*)x
                     + (size_t)b * CH * (HW / 4)
                     + chunk * 256 + tid;

    float acc[NB][4];
    #pragma unroll
    for (int n = 0; n < NB; n++)
        #pragma unroll
        for (int j = 0; j < 4; j++) acc[n][j] = 0.f;

    for (int c = 0; c < CH; c++) {
        float4 v = xb[(size_t)c * (HW / 4)];
        float w0 = s_wa[0 * CH + c];
        float w1 = s_wa[1 * CH + c];
        float w2 = s_wa[2 * CH + c];
        float w3 = s_wa[3 * CH + c];
        acc[0][0] += w0 * v.x; acc[0][1] += w0 * v.y; acc[0][2] += w0 * v.z; acc[0][3] += w0 * v.w;
        acc[1][0] += w1 * v.x; acc[1][1] += w1 * v.y; acc[1][2] += w1 * v.z; acc[1][3] += w1 * v.w;
        acc[2][0] += w2 * v.x; acc[2][1] += w2 * v.y; acc[2][2] += w2 * v.z; acc[2][3] += w2 * v.w;
        acc[3][0] += w3 * v.x; acc[3][1] += w3 * v.y; acc[3][2] += w3 * v.z; acc[3][3] += w3 * v.w;

        float s = v.x + v.y + v.z + v.w;
        #pragma unroll
        for (int o = 16; o > 0; o >>= 1) s += __shfl_down_sync(0xffffffffu, s, o);
        if (lane == 0) atomicAdd(&g_pooled[b * CH + c], s);
    }

    const float bb0 = b_attn[0], bb1 = b_attn[1], bb2 = b_attn[2], bb3 = b_attn[3];
    float ap[NB] = {0.f, 0.f, 0.f, 0.f};
    #pragma unroll
    for (int j = 0; j < 4; j++) {
        float l0 = acc[0][j] + bb0;
        float l1 = acc[1][j] + bb1;
        float l2 = acc[2][j] + bb2;
        float l3 = acc[3][j] + bb3;
        float m  = fmaxf(fmaxf(l0, l1), fmaxf(l2, l3));
        float e0 = __expf(l0 - m);
        float e1 = __expf(l1 - m);
        float e2 = __expf(l2 - m);
        float e3 = __expf(l3 - m);
        float inv = 1.f / (e0 + e1 + e2 + e3);
        ap[0] += e0 * inv; ap[1] += e1 * inv; ap[2] += e2 * inv; ap[3] += e3 * inv;
    }
    #pragma unroll
    for (int n = 0; n < NB; n++) {
        float s = ap[n];
        #pragma unroll
        for (int o = 16; o > 0; o >>= 1) s += __shfl_down_sync(0xffffffffu, s, o);
        if (lane == 0) atomicAdd(&g_attn[b * NB + n], s);
    }
}

// ============================================================
// pass 2: bases[b, row] = dot(w_base[row,:], pooled[b,:]) + b_base[row]
// grid 36 x 128; each thread = one w_base row, all 32 batches.
// ============================================================
__global__ void __launch_bounds__(128) k_bases(
    const float* __restrict__ w_base,
    const float* __restrict__ b_base)
{
    const int row = blockIdx.x * 128 + threadIdx.x;   // 0..4607

    __shared__ float s_pool[BATCH * CH];              // pooled MEANS
    for (int i = threadIdx.x; i < BATCH * CH; i += 128)
        s_pool[i] = g_pooled[i] * (1.0f / HW);
    __syncthreads();

    float acc[BATCH];
    const float bb = b_base[row];
    #pragma unroll
    for (int b = 0; b < BATCH; b++) acc[b] = bb;

    const float4* wr = (const float4*)(w_base + (size_t)row * CH);
    const float4* pp = (const float4*)s_pool;
    for (int c4 = 0; c4 < CH / 4; c4++) {
        float4 wv = wr[c4];
        #pragma unroll
        for (int b = 0; b < BATCH; b++) {
            float4 pv = pp[b * (CH / 4) + c4];
            acc[b] += wv.x * pv.x + wv.y * pv.y + wv.z * pv.z + wv.w * pv.w;
        }
    }
    #pragma unroll
    for (int b = 0; b < BATCH; b++)
        g_bases[(size_t)b * NROWS + row] = acc[b];
}

// ============================================================
// pass 3: per-sample 3x3 conv PARTIAL over a 32-channel group.
// grid (8 row-tiles, 4 ch-groups, 32 batch) = 1024 blocks, 128 threads.
// Software pipeline: LDG-prefetch next channel into registers while
// computing current channel from smem (no cp.async, no inline PTX).
// ============================================================
#define TILE_ROWS 16
#define NVEC ((TILE_ROWS + 2) * 32)   // 576 float4 per channel tile
__global__ void __launch_bounds__(128) k_conv(
    const float* __restrict__ x)
{
    const int b    = blockIdx.z;
    const int grp  = blockIdx.y;
    const int c0   = grp * CG;
    const int r0   = blockIdx.x * TILE_ROWS;
    const int tid  = threadIdx.x;
    const int th   = tid >> 5;      // warp id 0..3 -> 4-row band
    const int lane = tid & 31;      // 4 cols each -> 128 wide

    __shared__ float skern[CG * KK];                 // 1.1 KB
    __shared__ float stile[TILE_ROWS + 2][WDIM];     // 9.2 KB

    // build per-sample kernel slice for this channel group
    {
        float a[NB];
        #pragma unroll
        for (int n = 0; n < NB; n++)
            a[n] = g_attn[b * NB + n] * (1.0f / HW);
        for (int i = tid; i < CG * KK; i += 128) {
            float s = 0.f;
            #pragma unroll
            for (int n = 0; n < NB; n++)
                s += a[n] * g_bases[(size_t)b * NROWS + n * (CH * KK) + c0 * KK + i];
            skern[i] = s;
        }
    }

    float acc[4][4];
    #pragma unroll
    for (int k = 0; k < 4; k++)
        #pragma unroll
        for (int m = 0; m < 4; m++) acc[k][m] = 0.f;

    const float* xb = x + ((size_t)b * CH + c0) * HW;

    float4 pf[5];

    // prefetch channel cc's tile into registers (no smem, no sync)
    auto prefetch = [&](int cc) {
        const float* xc = xb + (size_t)cc * HW;
        #pragma unroll
        for (int j = 0; j < 5; j++) {
            int idx = tid + j * 128;
            if (idx < NVEC) {
                int i  = idx >> 5;               // smem row 0..17
                int f  = idx & 31;               // float4 within row
                int gr = r0 - 1 + i;
                if (gr >= 0 && gr < HDIM)
                    pf[j] = ((const float4*)(xc + (size_t)gr * WDIM))[f];
                else
                    pf[j] = make_float4(0.f, 0.f, 0.f, 0.f);
            }
        }
    };

    prefetch(0);

    for (int cc = 0; cc < CG; cc++) {
        __syncthreads();       // previous compute finished reading stile
        #pragma unroll
        for (int j = 0; j < 5; j++) {
            int idx = tid + j * 128;
            if (idx < NVEC)
                ((float4*)stile[idx >> 5])[idx & 31] = pf[j];
        }
        __syncthreads();

        if (cc + 1 < CG) prefetch(cc + 1);   // LDGs overlap the FFMA block below

        float kc[KK];
        #pragma unroll
        for (int q = 0; q < KK; q++) kc[q] = skern[cc * KK + q];

        #pragma unroll
        for (int ir = 0; ir < 6; ir++) {
            const int srow = th * 4 + ir;
            float4 v = ((const float4*)stile[srow])[lane];
            float u0 = __shfl_up_sync(0xffffffffu, v.w, 1);
            if (lane == 0)  u0 = 0.f;        // col -1 = zero pad
            float u5 = __shfl_down_sync(0xffffffffu, v.x, 1);
            if (lane == 31) u5 = 0.f;        // col 128 = zero pad
            float u[6] = {u0, v.x, v.y, v.z, v.w, u5};
            #pragma unroll
            for (int k = 0; k < 4; k++) {
                const int dy = ir - k;
                if (dy >= 0 && dy <= 2) {
                    #pragma unroll
                    for (int m = 0; m < 4; m++)
                        #pragma unroll
                        for (int dx = 0; dx < 3; dx++)
                            acc[k][m] += u[m + dx] * kc[dy * 3 + dx];
                }
            }
        }
    }

    float* po = g_part + ((size_t)grp * BATCH + b) * HW;
    #pragma unroll
    for (int k = 0; k < 4; k++) {
        int r = r0 + th * 4 + k;
        float4 o = make_float4(acc[k][0], acc[k][1], acc[k][2], acc[k][3]);
        ((float4*)(po + (size_t)r * WDIM))[lane] = o;
    }
}

// ============================================================
// pass 4: sum the 4 channel-group partials -> out
// ============================================================
__global__ void __launch_bounds__(256) k_reduce(float* __restrict__ out)
{
    int i = blockIdx.x * 256 + threadIdx.x;           // float4 index
    const int N4 = BATCH * HW / 4;                    // 131072 (multiple of 256)
    if (i >= N4) return;
    const float4* p = (const float4*)g_part;
    float4 a = p[i];
    float4 b = p[i + N4];
    float4 c = p[i + 2 * N4];
    float4 d = p[i + 3 * N4];
    float4 o = make_float4(a.x + b.x + c.x + d.x,
                           a.y + b.y + c.y + d.y,
                           a.z + b.z + c.z + d.z,
                           a.w + b.w + c.w + d.w);
    ((float4*)out)[i] = o;
}

// ============================================================
extern "C" void kernel_launch(void* const* d_in, const int* in_sizes, int n_in,
                              void* d_out, int out_size)
{
    const float* x      = (const float*)d_in[0];
    const float* w_base = (const float*)d_in[1];
    const float* b_base = (const float*)d_in[2];
    const float* w_attn = (const float*)d_in[3];
    const float* b_attn = (const float*)d_in[4];
    float* out = (float*)d_out;

    k_init  <<<16, 256>>>();
    k_stats <<<dim3(16, BATCH), 256>>>(x, w_attn, b_attn);
    k_bases <<<NROWS / 128, 128>>>(w_base, b_base);
    k_conv  <<<dim3(HDIM / TILE_ROWS, NGRP, BATCH), 128>>>(x);
    k_reduce<<<BATCH * HW / 4 / 256, 256>>>(out);
}

// round 7
// speedup vs baseline: 3.2393x; 1.1794x over previous
#include <cuda_runtime.h>
#include <cstdint>

#define BATCH 32
#define CH    128
#define HDIM  128
#define WDIM  128
#define HW    16384        // HDIM*WDIM
#define NB    4
#define KK    9            // 3x3
#define NROWS (NB*CH*KK)   // 4608 rows of w_base
#define NGRP  4            // channel groups in conv
#define CG    (CH/NGRP)    // 32 channels per group

// ---- scratch (device globals; no allocation allowed) ----
__device__ float g_pooled[BATCH * CH];              // channel sums (atomic)
__device__ float g_attn[BATCH * NB];                // softmax sums (atomic)
__device__ float g_bases[(size_t)BATCH * NROWS];    // per-sample base kernels
__device__ float g_part[(size_t)NGRP * BATCH * HW]; // conv partials (8 MB)

// ============================================================
// init: zero the atomic accumulators
// ============================================================
__global__ void k_init() {
    int idx = blockIdx.x * 256 + threadIdx.x;
    if (idx < BATCH * CH) g_pooled[idx] = 0.f;
    if (idx < BATCH * NB) g_attn[idx]   = 0.f;
}

// 16 FFMAs: acc[n][j] += w[n] * v[j]  (w = per-channel weights for 4 bases)
__device__ __forceinline__ void accum4(float acc[NB][4], float4 v, float4 w) {
    acc[0][0] += w.x * v.x; acc[0][1] += w.x * v.y;
    acc[0][2] += w.x * v.z; acc[0][3] += w.x * v.w;
    acc[1][0] += w.y * v.x; acc[1][1] += w.y * v.y;
    acc[1][2] += w.y * v.z; acc[1][3] += w.y * v.w;
    acc[2][0] += w.z * v.x; acc[2][1] += w.z * v.y;
    acc[2][2] += w.z * v.z; acc[2][3] += w.z * v.w;
    acc[3][0] += w.w * v.x; acc[3][1] += w.w * v.y;
    acc[3][2] += w.w * v.z; acc[3][3] += w.w * v.w;
}

// ============================================================
// pass 1: fused pooled-sum + attention logits + softmax + spatial mean
// grid (16 chunks, 32 batch), 256 threads; each thread owns 4 pixels.
// Channel loop unrolled x4: MLP>=4 on the LDG.128s, interleaved SHFL trees.
// ============================================================
__global__ void __launch_bounds__(256) k_stats(
    const float* __restrict__ x,
    const float* __restrict__ w_attn,
    const float* __restrict__ b_attn)
{
    const int b     = blockIdx.y;
    const int chunk = blockIdx.x;     // 0..15, 1024 pixels each
    const int tid   = threadIdx.x;    // 0..255
    const int lane  = tid & 31;

    // transposed weights: s_wat[c][n] -> one broadcast LDS.128 per channel
    __shared__ float s_wat[CH * NB];
    for (int i = tid; i < NB * CH; i += 256) {
        int n = i / CH;
        int c = i % CH;
        s_wat[c * NB + n] = w_attn[i];
    }
    __syncthreads();

    const float4* xb = (const float4*)x
                     + (size_t)b * CH * (HW / 4)
                     + chunk * 256 + tid;

    float acc[NB][4];
    #pragma unroll
    for (int n = 0; n < NB; n++)
        #pragma unroll
        for (int j = 0; j < 4; j++) acc[n][j] = 0.f;

    for (int c = 0; c < CH; c += 4) {
        // 4 independent loads in flight
        float4 v0 = xb[(size_t)(c + 0) * (HW / 4)];
        float4 v1 = xb[(size_t)(c + 1) * (HW / 4)];
        float4 v2 = xb[(size_t)(c + 2) * (HW / 4)];
        float4 v3 = xb[(size_t)(c + 3) * (HW / 4)];

        float4 w0 = ((const float4*)s_wat)[c + 0];   // w[n=0..3] for channel c
        float4 w1 = ((const float4*)s_wat)[c + 1];
        float4 w2 = ((const float4*)s_wat)[c + 2];
        float4 w3 = ((const float4*)s_wat)[c + 3];

        accum4(acc, v0, w0);
        accum4(acc, v1, w1);
        accum4(acc, v2, w2);
        accum4(acc, v3, w3);

        // pooled channel sums: 4 interleaved warp-reduce trees
        float s0 = (v0.x + v0.y) + (v0.z + v0.w);
        float s1 = (v1.x + v1.y) + (v1.z + v1.w);
        float s2 = (v2.x + v2.y) + (v2.z + v2.w);
        float s3 = (v3.x + v3.y) + (v3.z + v3.w);
        #pragma unroll
        for (int o = 16; o > 0; o >>= 1) {
            s0 += __shfl_down_sync(0xffffffffu, s0, o);
            s1 += __shfl_down_sync(0xffffffffu, s1, o);
            s2 += __shfl_down_sync(0xffffffffu, s2, o);
            s3 += __shfl_down_sync(0xffffffffu, s3, o);
        }
        if (lane == 0) {
            atomicAdd(&g_pooled[b * CH + c + 0], s0);
            atomicAdd(&g_pooled[b * CH + c + 1], s1);
            atomicAdd(&g_pooled[b * CH + c + 2], s2);
            atomicAdd(&g_pooled[b * CH + c + 3], s3);
        }
    }

    const float bb0 = b_attn[0];
    const float bb1 = b_attn[1];
    const float bb2 = b_attn[2];
    const float bb3 = b_attn[3];
    float ap0 = 0.f, ap1 = 0.f, ap2 = 0.f, ap3 = 0.f;
    #pragma unroll
    for (int j = 0; j < 4; j++) {
        float l0 = acc[0][j] + bb0;
        float l1 = acc[1][j] + bb1;
        float l2 = acc[2][j] + bb2;
        float l3 = acc[3][j] + bb3;
        float m  = fmaxf(fmaxf(l0, l1), fmaxf(l2, l3));
        float e0 = __expf(l0 - m);
        float e1 = __expf(l1 - m);
        float e2 = __expf(l2 - m);
        float e3 = __expf(l3 - m);
        float inv = 1.f / (e0 + e1 + e2 + e3);
        ap0 += e0 * inv;
        ap1 += e1 * inv;
        ap2 += e2 * inv;
        ap3 += e3 * inv;
    }
    #pragma unroll
    for (int o = 16; o > 0; o >>= 1) {
        ap0 += __shfl_down_sync(0xffffffffu, ap0, o);
        ap1 += __shfl_down_sync(0xffffffffu, ap1, o);
        ap2 += __shfl_down_sync(0xffffffffu, ap2, o);
        ap3 += __shfl_down_sync(0xffffffffu, ap3, o);
    }
    if (lane == 0) {
        atomicAdd(&g_attn[b * NB + 0], ap0);
        atomicAdd(&g_attn[b * NB + 1], ap1);
        atomicAdd(&g_attn[b * NB + 2], ap2);
        atomicAdd(&g_attn[b * NB + 3], ap3);
    }
}

// ============================================================
// pass 2: bases[b, row] = dot(w_base[row,:], pooled[b,:]) + b_base[row]
// grid 36 x 128; each thread = one w_base row, all 32 batches.
// ============================================================
__global__ void __launch_bounds__(128) k_bases(
    const float* __restrict__ w_base,
    const float* __restrict__ b_base)
{
    const int row = blockIdx.x * 128 + threadIdx.x;   // 0..4607

    __shared__ float s_pool[BATCH * CH];              // pooled MEANS
    for (int i = threadIdx.x; i < BATCH * CH; i += 128)
        s_pool[i] = g_pooled[i] * (1.0f / HW);
    __syncthreads();

    float acc[BATCH];
    const float bb = b_base[row];
    #pragma unroll
    for (int b = 0; b < BATCH; b++) acc[b] = bb;

    const float4* wr = (const float4*)(w_base + (size_t)row * CH);
    const float4* pp = (const float4*)s_pool;
    for (int c4 = 0; c4 < CH / 4; c4++) {
        float4 wv = wr[c4];
        #pragma unroll
        for (int b = 0; b < BATCH; b++) {
            float4 pv = pp[b * (CH / 4) + c4];
            acc[b] += wv.x * pv.x + wv.y * pv.y + wv.z * pv.z + wv.w * pv.w;
        }
    }
    #pragma unroll
    for (int b = 0; b < BATCH; b++)
        g_bases[(size_t)b * NROWS + row] = acc[b];
}

// ============================================================
// pass 3: per-sample 3x3 conv PARTIAL over a 32-channel group.
// grid (8 row-tiles, 4 ch-groups, 32 batch) = 1024 blocks, 128 threads.
// Register-prefetch software pipeline (proven in R4).
// ============================================================
#define TILE_ROWS 16
#define NVEC ((TILE_ROWS + 2) * 32)   // 576 float4 per channel tile
__global__ void __launch_bounds__(128) k_conv(
    const float* __restrict__ x)
{
    const int b    = blockIdx.z;
    const int grp  = blockIdx.y;
    const int c0   = grp * CG;
    const int r0   = blockIdx.x * TILE_ROWS;
    const int tid  = threadIdx.x;
    const int th   = tid >> 5;      // warp id 0..3 -> 4-row band
    const int lane = tid & 31;      // 4 cols each -> 128 wide

    __shared__ float skern[CG * KK];                 // 1.1 KB
    __shared__ float stile[TILE_ROWS + 2][WDIM];     // 9.2 KB

    // build per-sample kernel slice for this channel group
    {
        float a0 = g_attn[b * NB + 0] * (1.0f / HW);
        float a1 = g_attn[b * NB + 1] * (1.0f / HW);
        float a2 = g_attn[b * NB + 2] * (1.0f / HW);
        float a3 = g_attn[b * NB + 3] * (1.0f / HW);
        const float* gb = g_bases + (size_t)b * NROWS + c0 * KK;
        for (int i = tid; i < CG * KK; i += 128) {
            float s = a0 * gb[0 * (CH * KK) + i]
                    + a1 * gb[1 * (CH * KK) + i]
                    + a2 * gb[2 * (CH * KK) + i]
                    + a3 * gb[3 * (CH * KK) + i];
            skern[i] = s;
        }
    }

    float acc[4][4];
    #pragma unroll
    for (int k = 0; k < 4; k++)
        #pragma unroll
        for (int m = 0; m < 4; m++) acc[k][m] = 0.f;

    const float* xb = x + ((size_t)b * CH + c0) * HW;

    float4 pf[5];

    auto prefetch = [&](int cc) {
        const float* xc = xb + (size_t)cc * HW;
        #pragma unroll
        for (int j = 0; j < 5; j++) {
            int idx = tid + j * 128;
            if (idx < NVEC) {
                int i  = idx >> 5;               // smem row 0..17
                int f  = idx & 31;               // float4 within row
                int gr = r0 - 1 + i;
                if (gr >= 0 && gr < HDIM)
                    pf[j] = ((const float4*)(xc + (size_t)gr * WDIM))[f];
                else
                    pf[j] = make_float4(0.f, 0.f, 0.f, 0.f);
            }
        }
    };

    prefetch(0);

    for (int cc = 0; cc < CG; cc++) {
        __syncthreads();       // previous compute finished reading stile
        #pragma unroll
        for (int j = 0; j < 5; j++) {
            int idx = tid + j * 128;
            if (idx < NVEC)
                ((float4*)stile[idx >> 5])[idx & 31] = pf[j];
        }
        __syncthreads();

        if (cc + 1 < CG) prefetch(cc + 1);   // LDGs overlap the FFMA block below

        float kc[KK];
        #pragma unroll
        for (int q = 0; q < KK; q++) kc[q] = skern[cc * KK + q];

        #pragma unroll
        for (int ir = 0; ir < 6; ir++) {
            const int srow = th * 4 + ir;
            float4 v = ((const float4*)stile[srow])[lane];
            float u0 = __shfl_up_sync(0xffffffffu, v.w, 1);
            if (lane == 0)  u0 = 0.f;        // col -1 = zero pad
            float u5 = __shfl_down_sync(0xffffffffu, v.x, 1);
            if (lane == 31) u5 = 0.f;        // col 128 = zero pad
            float u[6] = {u0, v.x, v.y, v.z, v.w, u5};
            #pragma unroll
            for (int k = 0; k < 4; k++) {
                const int dy = ir - k;
                if (dy >= 0 && dy <= 2) {
                    #pragma unroll
                    for (int m = 0; m < 4; m++)
                        #pragma unroll
                        for (int dx = 0; dx < 3; dx++)
                            acc[k][m] += u[m + dx] * kc[dy * 3 + dx];
                }
            }
        }
    }

    float* po = g_part + ((size_t)grp * BATCH + b) * HW;
    #pragma unroll
    for (int k = 0; k < 4; k++) {
        int r = r0 + th * 4 + k;
        float4 o = make_float4(acc[k][0], acc[k][1], acc[k][2], acc[k][3]);
        ((float4*)(po + (size_t)r * WDIM))[lane] = o;
    }
}

// ============================================================
// pass 4: sum the 4 channel-group partials -> out
// ============================================================
__global__ void __launch_bounds__(256) k_reduce(float* __restrict__ out)
{
    int i = blockIdx.x * 256 + threadIdx.x;           // float4 index
    const int N4 = BATCH * HW / 4;                    // 131072 (multiple of 256)
    if (i >= N4) return;
    const float4* p = (const float4*)g_part;
    float4 a = p[i];
    float4 b = p[i + N4];
    float4 c = p[i + 2 * N4];
    float4 d = p[i + 3 * N4];
    float4 o = make_float4(a.x + b.x + c.x + d.x,
                           a.y + b.y + c.y + d.y,
                           a.z + b.z + c.z + d.z,
                           a.w + b.w + c.w + d.w);
    ((float4*)out)[i] = o;
}

// ============================================================
extern "C" void kernel_launch(void* const* d_in, const int* in_sizes, int n_in,
                              void* d_out, int out_size)
{
    const float* x      = (const float*)d_in[0];
    const float* w_base = (const float*)d_in[1];
    const float* b_base = (const float*)d_in[2];
    const float* w_attn = (const float*)d_in[3];
    const float* b_attn = (const float*)d_in[4];
    float* out = (float*)d_out;

    k_init  <<<16, 256>>>();
    k_stats <<<dim3(16, BATCH), 256>>>(x, w_attn, b_attn);
    k_bases <<<NROWS / 128, 128>>>(w_base, b_base);
    k_conv  <<<dim3(HDIM / TILE_ROWS, NGRP, BATCH), 128>>>(x);
    k_reduce<<<BATCH * HW / 4 / 256, 256>>>(out);
}

// round 10
// speedup vs baseline: 3.5930x; 1.1092x over previous
#include <cuda_runtime.h>
#include <cstdint>

#define BATCH 32
#define CH    128
#define HDIM  128
#define WDIM  128
#define HW    16384        // HDIM*WDIM
#define NB    4
#define KK    9            // 3x3
#define NROWS (NB*CH*KK)   // 4608 rows of w_base
#define NGRP  4            // channel groups in conv
#define CG    (CH/NGRP)    // 32 channels per group
#define NCHUNK 16          // k_stats chunk-blocks per batch

// ---- scratch (device globals; no allocation allowed) ----
__device__ float g_pool_part[NCHUNK * BATCH * CH];  // per-chunk channel sums
__device__ float g_attn_part[NCHUNK * BATCH * NB];  // per-chunk softmax sums
__device__ float g_bases[(size_t)BATCH * NROWS];    // per-sample base kernels
__device__ float g_part[(size_t)NGRP * BATCH * HW]; // conv partials (8 MB)

// 16 FFMAs: acc[n][j] += w[n] * v[j]
__device__ __forceinline__ void accum4(float acc[NB][4], float4 v, float4 w) {
    acc[0][0] += w.x * v.x; acc[0][1] += w.x * v.y;
    acc[0][2] += w.x * v.z; acc[0][3] += w.x * v.w;
    acc[1][0] += w.y * v.x; acc[1][1] += w.y * v.y;
    acc[1][2] += w.y * v.z; acc[1][3] += w.y * v.w;
    acc[2][0] += w.z * v.x; acc[2][1] += w.z * v.y;
    acc[2][2] += w.z * v.z; acc[2][3] += w.z * v.w;
    acc[3][0] += w.w * v.x; acc[3][1] += w.w * v.y;
    acc[3][2] += w.w * v.z; acc[3][3] += w.w * v.w;
}

__device__ __forceinline__ float hsum4(float4 v) {
    return (v.x + v.y) + (v.z + v.w);
}

// ============================================================
// pass 1: fused pooled-sum + attention logits + softmax + spatial mean
// grid (16 chunks, 32 batch), 256 threads; each thread owns 4 pixels.
// Channel loop unrolled x8 (MLP=8). NO atomics: per-warp sums -> smem,
// block partials -> g_pool_part / g_attn_part (summed downstream).
// ============================================================
__global__ void __launch_bounds__(256) k_stats(
    const float* __restrict__ x,
    const float* __restrict__ w_attn,
    const float* __restrict__ b_attn)
{
    const int b     = blockIdx.y;
    const int chunk = blockIdx.x;     // 0..15, 1024 pixels each
    const int tid   = threadIdx.x;    // 0..255
    const int th    = tid >> 5;       // warp 0..7
    const int lane  = tid & 31;

    // transposed weights: s_wat[c] = (w[0,c], w[1,c], w[2,c], w[3,c])
    __shared__ float s_wat[CH * NB];
    __shared__ float s_psum[8][CH];   // per-warp channel sums, 4 KB
    __shared__ float s_asum[8][NB];   // per-warp attention sums
    for (int i = tid; i < NB * CH; i += 256) {
        int n = i / CH;
        int c = i % CH;
        s_wat[c * NB + n] = w_attn[i];
    }
    __syncthreads();

    const float4* xb = (const float4*)x
                     + (size_t)b * CH * (HW / 4)
                     + chunk * 256 + tid;

    float acc[NB][4];
    #pragma unroll
    for (int n = 0; n < NB; n++)
        #pragma unroll
        for (int j = 0; j < 4; j++) acc[n][j] = 0.f;

    for (int c = 0; c < CH; c += 8) {
        // 8 independent LDG.128 in flight
        float4 v[8];
        #pragma unroll
        for (int q = 0; q < 8; q++)
            v[q] = xb[(size_t)(c + q) * (HW / 4)];

        #pragma unroll
        for (int q = 0; q < 8; q++) {
            float4 w = ((const float4*)s_wat)[c + q];
            accum4(acc, v[q], w);
        }

        // pooled channel sums: 8 interleaved warp-reduce trees
        float s[8];
        #pragma unroll
        for (int q = 0; q < 8; q++) s[q] = hsum4(v[q]);
        #pragma unroll
        for (int o = 16; o > 0; o >>= 1) {
            #pragma unroll
            for (int q = 0; q < 8; q++)
                s[q] += __shfl_down_sync(0xffffffffu, s[q], o);
        }
        if (lane == 0) {
            #pragma unroll
            for (int q = 0; q < 8; q++)
                s_psum[th][c + q] = s[q];
        }
    }

    // softmax over bases per pixel, then per-thread spatial partial
    const float bb0 = b_attn[0];
    const float bb1 = b_attn[1];
    const float bb2 = b_attn[2];
    const float bb3 = b_attn[3];
    float ap0 = 0.f, ap1 = 0.f, ap2 = 0.f, ap3 = 0.f;
    #pragma unroll
    for (int j = 0; j < 4; j++) {
        float l0 = acc[0][j] + bb0;
        float l1 = acc[1][j] + bb1;
        float l2 = acc[2][j] + bb2;
        float l3 = acc[3][j] + bb3;
        float m  = fmaxf(fmaxf(l0, l1), fmaxf(l2, l3));
        float e0 = __expf(l0 - m);
        float e1 = __expf(l1 - m);
        float e2 = __expf(l2 - m);
        float e3 = __expf(l3 - m);
        float inv = 1.f / (e0 + e1 + e2 + e3);
        ap0 += e0 * inv;
        ap1 += e1 * inv;
        ap2 += e2 * inv;
        ap3 += e3 * inv;
    }
    #pragma unroll
    for (int o = 16; o > 0; o >>= 1) {
        ap0 += __shfl_down_sync(0xffffffffu, ap0, o);
        ap1 += __shfl_down_sync(0xffffffffu, ap1, o);
        ap2 += __shfl_down_sync(0xffffffffu, ap2, o);
        ap3 += __shfl_down_sync(0xffffffffu, ap3, o);
    }
    if (lane == 0) {
        s_asum[th][0] = ap0;
        s_asum[th][1] = ap1;
        s_asum[th][2] = ap2;
        s_asum[th][3] = ap3;
    }
    __syncthreads();

    // block-level combine (8 warps) -> global partials, no atomics
    if (tid < CH) {
        float ps = 0.f;
        #pragma unroll
        for (int w = 0; w < 8; w++) ps += s_psum[w][tid];
        g_pool_part[(chunk * BATCH + b) * CH + tid] = ps;
    }
    if (tid < NB) {
        float as = 0.f;
        #pragma unroll
        for (int w = 0; w < 8; w++) as += s_asum[w][tid];
        g_attn_part[(chunk * BATCH + b) * NB + tid] = as;
    }
}

// ============================================================
// pass 2: bases[b, row] = dot(w_base[row,:], pooled[b,:]) + b_base[row]
// grid 36 x 128; each thread = one w_base row, all 32 batches.
// ============================================================
__global__ void __launch_bounds__(128) k_bases(
    const float* __restrict__ w_base,
    const float* __restrict__ b_base)
{
    const int row = blockIdx.x * 128 + threadIdx.x;   // 0..4607

    __shared__ float s_pool[BATCH * CH];              // pooled MEANS
    for (int i = threadIdx.x; i < BATCH * CH; i += 128) {
        float s = 0.f;
        #pragma unroll
        for (int k = 0; k < NCHUNK; k++)
            s += g_pool_part[k * (BATCH * CH) + i];
        s_pool[i] = s * (1.0f / HW);
    }
    __syncthreads();

    float acc[BATCH];
    const float bb = b_base[row];
    #pragma unroll
    for (int b = 0; b < BATCH; b++) acc[b] = bb;

    const float4* wr = (const float4*)(w_base + (size_t)row * CH);
    const float4* pp = (const float4*)s_pool;
    for (int c4 = 0; c4 < CH / 4; c4++) {
        float4 wv = wr[c4];
        #pragma unroll
        for (int b = 0; b < BATCH; b++) {
            float4 pv = pp[b * (CH / 4) + c4];
            acc[b] += wv.x * pv.x + wv.y * pv.y + wv.z * pv.z + wv.w * pv.w;
        }
    }
    #pragma unroll
    for (int b = 0; b < BATCH; b++)
        g_bases[(size_t)b * NROWS + row] = acc[b];
}

// ============================================================
// pass 3: per-sample 3x3 conv PARTIAL over a 32-channel group.
// grid (8 row-tiles, 4 ch-groups, 32 batch) = 1024 blocks, 128 threads.
// Register-prefetch software pipeline (proven R4/R7).
// ============================================================
#define TILE_ROWS 16
#define NVEC ((TILE_ROWS + 2) * 32)   // 576 float4 per channel tile
__global__ void __launch_bounds__(128) k_conv(
    const float* __restrict__ x)
{
    const int b    = blockIdx.z;
    const int grp  = blockIdx.y;
    const int c0   = grp * CG;
    const int r0   = blockIdx.x * TILE_ROWS;
    const int tid  = threadIdx.x;
    const int th   = tid >> 5;      // warp id 0..3 -> 4-row band
    const int lane = tid & 31;      // 4 cols each -> 128 wide

    __shared__ float skern[CG * KK];                 // 1.1 KB
    __shared__ float stile[TILE_ROWS + 2][WDIM];     // 9.2 KB

    // build per-sample kernel slice for this channel group
    {
        float a0 = 0.f, a1 = 0.f, a2 = 0.f, a3 = 0.f;
        for (int k = 0; k < NCHUNK; k++) {
            const float* ap = g_attn_part + (k * BATCH + b) * NB;
            a0 += ap[0]; a1 += ap[1]; a2 += ap[2]; a3 += ap[3];
        }
        a0 *= (1.0f / HW); a1 *= (1.0f / HW);
        a2 *= (1.0f / HW); a3 *= (1.0f / HW);
        const float* gb = g_bases + (size_t)b * NROWS + c0 * KK;
        for (int i = tid; i < CG * KK; i += 128) {
            float s = a0 * gb[0 * (CH * KK) + i]
                    + a1 * gb[1 * (CH * KK) + i]
                    + a2 * gb[2 * (CH * KK) + i]
                    + a3 * gb[3 * (CH * KK) + i];
            skern[i] = s;
        }
    }

    float acc[4][4];
    #pragma unroll
    for (int k = 0; k < 4; k++)
        #pragma unroll
        for (int m = 0; m < 4; m++) acc[k][m] = 0.f;

    const float* xb = x + ((size_t)b * CH + c0) * HW;

    float4 pf[5];

    auto prefetch = [&](int cc) {
        const float* xc = xb + (size_t)cc * HW;
        #pragma unroll
        for (int j = 0; j < 5; j++) {
            int idx = tid + j * 128;
            if (idx < NVEC) {
                int i  = idx >> 5;               // smem row 0..17
                int f  = idx & 31;               // float4 within row
                int gr = r0 - 1 + i;
                if (gr >= 0 && gr < HDIM)
                    pf[j] = ((const float4*)(xc + (size_t)gr * WDIM))[f];
                else
                    pf[j] = make_float4(0.f, 0.f, 0.f, 0.f);
            }
        }
    };

    prefetch(0);

    for (int cc = 0; cc < CG; cc++) {
        __syncthreads();       // previous compute finished reading stile
        #pragma unroll
        for (int j = 0; j < 5; j++) {
            int idx = tid + j * 128;
            if (idx < NVEC)
                ((float4*)stile[idx >> 5])[idx & 31] = pf[j];
        }
        __syncthreads();

        if (cc + 1 < CG) prefetch(cc + 1);   // LDGs overlap the FFMA block below

        float kc[KK];
        #pragma unroll
        for (int q = 0; q < KK; q++) kc[q] = skern[cc * KK + q];

        #pragma unroll
        for (int ir = 0; ir < 6; ir++) {
            const int srow = th * 4 + ir;
            float4 v = ((const float4*)stile[srow])[lane];
            float u0 = __shfl_up_sync(0xffffffffu, v.w, 1);
            if (lane == 0)  u0 = 0.f;        // col -1 = zero pad
            float u5 = __shfl_down_sync(0xffffffffu, v.x, 1);
            if (lane == 31) u5 = 0.f;        // col 128 = zero pad
            float u[6] = {u0, v.x, v.y, v.z, v.w, u5};
            #pragma unroll
            for (int k = 0; k < 4; k++) {
                const int dy = ir - k;
                if (dy >= 0 && dy <= 2) {
                    #pragma unroll
                    for (int m = 0; m < 4; m++)
                        #pragma unroll
                        for (int dx = 0; dx < 3; dx++)
                            acc[k][m] += u[m + dx] * kc[dy * 3 + dx];
                }
            }
        }
    }

    float* po = g_part + ((size_t)grp * BATCH + b) * HW;
    #pragma unroll
    for (int k = 0; k < 4; k++) {
        int r = r0 + th * 4 + k;
        float4 o = make_float4(acc[k][0], acc[k][1], acc[k][2], acc[k][3]);
        ((float4*)(po + (size_t)r * WDIM))[lane] = o;
    }
}

// ============================================================
// pass 4: sum the 4 channel-group partials -> out
// ============================================================
__global__ void __launch_bounds__(256) k_reduce(float* __restrict__ out)
{
    int i = blockIdx.x * 256 + threadIdx.x;           // float4 index
    const int N4 = BATCH * HW / 4;                    // 131072 (multiple of 256)
    if (i >= N4) return;
    const float4* p = (const float4*)g_part;
    float4 a = p[i];
    float4 b = p[i + N4];
    float4 c = p[i + 2 * N4];
    float4 d = p[i + 3 * N4];
    float4 o = make_float4(a.x + b.x + c.x + d.x,
                           a.y + b.y + c.y + d.y,
                           a.z + b.z + c.z + d.z,
                           a.w + b.w + c.w + d.w);
    ((float4*)out)[i] = o;
}

// ============================================================
extern "C" void kernel_launch(void* const* d_in, const int* in_sizes, int n_in,
                              void* d_out, int out_size)
{
    const float* x      = (const float*)d_in[0];
    const float* w_base = (const float*)d_in[1];
    const float* b_base = (const float*)d_in[2];
    const float* w_attn = (const float*)d_in[3];
    const float* b_attn = (const float*)d_in[4];
    float* out = (float*)d_out;

    k_stats <<<dim3(NCHUNK, BATCH), 256>>>(x, w_attn, b_attn);
    k_bases <<<NROWS / 128, 128>>>(w_base, b_base);
    k_conv  <<<dim3(HDIM / TILE_ROWS, NGRP, BATCH), 128>>>(x);
    k_reduce<<<BATCH * HW / 4 / 256, 256>>>(out);
}